// round 10
// baseline (speedup 1.0000x reference)
#include <cuda_runtime.h>
#include <cstdint>

// ============================================================================
// out[M,N] = (clip(round(x/inscale)) int8) @ weight[N,K]^T * alpha
// M=8192, K=4096, N=4096.  Plain-sm_103 ptxas target (no tcgen05).
// mma.sync.m16n8k32.s8 + cp.async pipeline, explicit per-thread fragment
// loads (no ldmatrix).  Device-side weight dtype detection: the harness type
// map may materialize the int8 weight as int32 or float32; we sample the
// buffer and normalize into an int8 scratch in all three cases.
// ============================================================================

#define MM 8192
#define NN 4096
#define KDIM 4096
#define BM 128
#define BN 128
#define BK 128                 // int8 elems (=bytes) per K-chunk
#define STAGES 4
#define THREADS 256
#define KITERS (KDIM / BK)     // 32

#define ASTAGE (BM * BK)                   // 16384 B
#define BSTAGE (BN * BK)                   // 16384 B
#define STAGE_BYTES (ASTAGE + BSTAGE)      // 32768 B
#define SMEM_TOTAL (STAGES * STAGE_BYTES)  // 131072 B

// device scratch (allocation-free)
__device__ int8_t g_q[(size_t)MM * (size_t)KDIM];   // quantized activations
__device__ int8_t g_w[(size_t)NN * (size_t)KDIM];   // normalized int8 weight
__device__ int    g_w_mode;                          // 0=int8, 1=int32, 2=f32

// ---------------------------------------------------------------------------
__device__ __forceinline__ uint32_t smem_u32(const void* p) {
    uint32_t a;
    asm("{ .reg .u64 t; cvta.to.shared.u64 t, %1; cvt.u32.u64 %0, t; }"
        : "=r"(a) : "l"(p));
    return a;
}

__device__ __forceinline__ void cp16(uint32_t dst, const void* src) {
    asm volatile("cp.async.cg.shared.global [%0], [%1], 16;"
                 :: "r"(dst), "l"(src));
}

#define CP_COMMIT() asm volatile("cp.async.commit_group;" ::: "memory")
#define CP_WAIT2()  asm volatile("cp.async.wait_group 2;" ::: "memory")

__device__ __forceinline__ uint32_t lds32(uint32_t addr) {
    uint32_t v;
    asm volatile("ld.shared.b32 %0, [%1];" : "=r"(v) : "r"(addr));
    return v;
}

__device__ __forceinline__ void mma_s8(int* c, const uint32_t* a, const uint32_t* b) {
    asm volatile(
        "mma.sync.aligned.m16n8k32.row.col.s32.s8.s8.s32 "
        "{%0,%1,%2,%3}, {%4,%5,%6,%7}, {%8,%9}, {%0,%1,%2,%3};"
        : "+r"(c[0]), "+r"(c[1]), "+r"(c[2]), "+r"(c[3])
        : "r"(a[0]), "r"(a[1]), "r"(a[2]), "r"(a[3]), "r"(b[0]), "r"(b[1]));
}

// XOR swizzle for 128-byte rows: chunk(16B) index ^= (row & 7).
// Same bijection for cp.async stores and fragment loads; conflict-free.
__device__ __forceinline__ uint32_t swz(int row, int chunk16) {
    return (uint32_t)(row * 128) + (uint32_t)((chunk16 ^ (row & 7)) * 16);
}

// ---------------------------------------------------------------------------
// Kernel 0a: detect weight storage format from the first 8192 32-bit words.
//   int32 storage: every word in [-128,127]        (raw int8: p ~ 2^-24/word)
//   float32 storage: every word is a float with integral value, |v| <= 127
//     (int32 small values reinterpret to denormals -> fail integrality;
//      float values reinterpret to huge int32 -> fail the int32 test)
// Single block; writes the flag unconditionally every launch (deterministic).
// ---------------------------------------------------------------------------
__global__ void detect_kernel(const int* __restrict__ w) {
    __shared__ int cnt_i32, cnt_f32;
    if (threadIdx.x == 0) { cnt_i32 = 0; cnt_f32 = 0; }
    __syncthreads();
    int li = 0, lf = 0;
    for (int j = 0; j < 32; j++) {
        int v = w[threadIdx.x * 32 + j];
        if (v >= -128 && v <= 127) li++;
        float f = __int_as_float(v);
        if (f == rintf(f) && fabsf(f) <= 127.0f) lf++;
    }
    atomicAdd(&cnt_i32, li);
    atomicAdd(&cnt_f32, lf);
    __syncthreads();
    if (threadIdx.x == 0) {
        int mode = 0;
        if (cnt_i32 >= 4096) mode = 1;
        else if (cnt_f32 >= 4096) mode = 2;
        g_w_mode = mode;
    }
}

// Kernel 0b: normalize weight into int8 scratch.
__global__ void __launch_bounds__(256) convert_w_kernel(const void* __restrict__ w) {
    const size_t i = (size_t)blockIdx.x * blockDim.x + threadIdx.x;  // char4 idx
    const int mode = g_w_mode;
    char4 c;
    if (mode == 1) {
        int4 v = reinterpret_cast<const int4*>(w)[i];
        c.x = (char)v.x; c.y = (char)v.y; c.z = (char)v.z; c.w = (char)v.w;
    } else if (mode == 2) {
        float4 v = reinterpret_cast<const float4*>(w)[i];
        c.x = (char)(int)v.x; c.y = (char)(int)v.y;
        c.z = (char)(int)v.z; c.w = (char)(int)v.w;
    } else {
        c = reinterpret_cast<const char4*>(w)[i];
    }
    reinterpret_cast<char4*>(g_w)[i] = c;
}

// ---------------------------------------------------------------------------
// Kernel 1: fp32 -> int8 per-tensor quantization.
// __fdiv_rn: IEEE division even under --use_fast_math, so rintf() bit-matches
// jnp.round(xf / inscale) (round-half-even on the exact quotient).
// ---------------------------------------------------------------------------
__global__ void __launch_bounds__(256) quant_kernel(const float* __restrict__ x,
                                                    const float* __restrict__ inscale_p) {
    const float s = *inscale_p;
    size_t i = (size_t)blockIdx.x * blockDim.x + threadIdx.x;  // float4 index
    float4 v = reinterpret_cast<const float4*>(x)[i];
    char4 q;
    q.x = (char)(int)fminf(127.f, fmaxf(-128.f, rintf(__fdiv_rn(v.x, s))));
    q.y = (char)(int)fminf(127.f, fmaxf(-128.f, rintf(__fdiv_rn(v.y, s))));
    q.z = (char)(int)fminf(127.f, fmaxf(-128.f, rintf(__fdiv_rn(v.z, s))));
    q.w = (char)(int)fminf(127.f, fmaxf(-128.f, rintf(__fdiv_rn(v.w, s))));
    reinterpret_cast<char4*>(g_q)[i] = q;
}

// ---------------------------------------------------------------------------
// Kernel 2: int8 tensor-core GEMM (mma.sync) + fused alpha-dequant epilogue
// ---------------------------------------------------------------------------
__global__ void __launch_bounds__(THREADS, 1)
gemm_kernel(float* __restrict__ out, const float* __restrict__ alpha_p) {
    extern __shared__ char smem[];
    const uint32_t sbase = smem_u32(smem);
    const int tid = threadIdx.x;
    const int wid = tid >> 5;
    const int lid = tid & 31;

    // tile swizzle: groups of 16 M-tiles sweep all N-tiles (L2 reuse)
    const int grid_n = NN / BN;                 // 32
    const int pid = blockIdx.x;
    const int group = pid / (16 * grid_n);
    const int rem = pid % (16 * grid_n);
    const int tile_m = group * 16 + (rem & 15);
    const int tile_n = rem >> 4;
    const int m0 = tile_m * BM;
    const int n0 = tile_n * BN;

    const int warp_m = wid & 3;                 // 4 warps along M
    const int warp_n = wid >> 2;                // 2 warps along N

    const int8_t* aptr = g_q + (size_t)m0 * KDIM;
    const int8_t* bptr = g_w + (size_t)n0 * KDIM;

    int acc[2][8][4] = {};

    // PTX-ISA m16n8k32.s8 fragment addresses (explicit scalar loads):
    //  A a0: row = warp_m*32 + mi*16 + lid/4, k-bytes 4*(lid%4) of chunk 2ks
    //    a1: row+8 same chunk; a2/a3: chunk 2ks+1
    //  B b0: n = warp_n*64 + ni*8 + lid/4, chunk 2ks;  b1: chunk 2ks+1
    const int frow = lid >> 2;            // 0..7
    const int fbyte = (lid & 3) * 4;      // 0,4,8,12

    auto load_stage = [&](int kit, int stg) {
        const uint32_t abase = sbase + stg * STAGE_BYTES;
        const uint32_t bbase = abase + ASTAGE;
        const int kk0 = kit * BK;
#pragma unroll
        for (int i = 0; i < 4; i++) {           // A: 128 rows x 8 chunks
            int idx = tid + i * THREADS;
            int row = idx >> 3, c = idx & 7;
            cp16(abase + swz(row, c), aptr + (size_t)row * KDIM + kk0 + c * 16);
        }
#pragma unroll
        for (int i = 0; i < 4; i++) {           // B: 128 rows x 8 chunks
            int idx = tid + i * THREADS;
            int row = idx >> 3, c = idx & 7;
            cp16(bbase + swz(row, c), bptr + (size_t)row * KDIM + kk0 + c * 16);
        }
    };

    auto load_frags = [&](uint32_t abase, uint32_t bbase, int ks,
                          uint32_t af[2][4], uint32_t bf[8][2]) {
        const int c0 = ks * 2, c1 = ks * 2 + 1;
#pragma unroll
        for (int mi = 0; mi < 2; mi++) {
            const int r = warp_m * 32 + mi * 16 + frow;
            af[mi][0] = lds32(abase + swz(r,     c0) + fbyte);
            af[mi][1] = lds32(abase + swz(r + 8, c0) + fbyte);
            af[mi][2] = lds32(abase + swz(r,     c1) + fbyte);
            af[mi][3] = lds32(abase + swz(r + 8, c1) + fbyte);
        }
#pragma unroll
        for (int ni = 0; ni < 8; ni++) {
            const int r = warp_n * 64 + ni * 8 + frow;
            bf[ni][0] = lds32(bbase + swz(r, c0) + fbyte);
            bf[ni][1] = lds32(bbase + swz(r, c1) + fbyte);
        }
    };

    // software-pipelined compute: prefetch step ks+1 fragments before ks MMAs
    auto compute_stage = [&](int stg) {
        const uint32_t abase = sbase + stg * STAGE_BYTES;
        const uint32_t bbase = abase + ASTAGE;
        uint32_t af[2][2][4];
        uint32_t bf[2][8][2];
        load_frags(abase, bbase, 0, af[0], bf[0]);
#pragma unroll
        for (int ks = 0; ks < 4; ks++) {
            const int cur = ks & 1, nxt = cur ^ 1;
            if (ks < 3) load_frags(abase, bbase, ks + 1, af[nxt], bf[nxt]);
#pragma unroll
            for (int mi = 0; mi < 2; mi++)
#pragma unroll
                for (int ni = 0; ni < 8; ni++)
                    mma_s8(acc[mi][ni], af[cur][mi], bf[cur][ni]);
        }
    };

    // prologue: fill STAGES-1 stages
#pragma unroll
    for (int s = 0; s < STAGES - 1; s++) {
        load_stage(s, s);
        CP_COMMIT();
    }

    for (int k = 0; k < KITERS; k++) {
        CP_WAIT2();          // stage k's group complete (<=2 groups pending)
        __syncthreads();     // all warps done with the buffer we refill next
        const int kn = k + STAGES - 1;
        if (kn < KITERS) load_stage(kn, kn & (STAGES - 1));
        CP_COMMIT();         // (possibly empty group: keeps count aligned)
        compute_stage(k & (STAGES - 1));
    }

    // epilogue: alpha-dequant, float2 stores.
    // C fragment m16n8.s32: c0/c1 -> (row lid/4, col 2*(lid%4)+{0,1});
    //                       c2/c3 -> row+8, same cols.
    const float alpha = *alpha_p;
    const int r0 = m0 + warp_m * 32 + (lid >> 2);
    const int c0 = n0 + warp_n * 64 + (lid & 3) * 2;
#pragma unroll
    for (int mi = 0; mi < 2; mi++) {
#pragma unroll
        for (int ni = 0; ni < 8; ni++) {
            const int row = r0 + mi * 16;
            const int col = c0 + ni * 8;
            float2 v0, v1;
            v0.x = (float)acc[mi][ni][0] * alpha;
            v0.y = (float)acc[mi][ni][1] * alpha;
            v1.x = (float)acc[mi][ni][2] * alpha;
            v1.y = (float)acc[mi][ni][3] * alpha;
            *reinterpret_cast<float2*>(out + (size_t)row * NN + col) = v0;
            *reinterpret_cast<float2*>(out + (size_t)(row + 8) * NN + col) = v1;
        }
    }
}

// ---------------------------------------------------------------------------
extern "C" void kernel_launch(void* const* d_in, const int* in_sizes, int n_in,
                              void* d_out, int out_size) {
    const float* x       = (const float*)d_in[0];
    const void*  w       = d_in[1];
    const float* alpha   = (const float*)d_in[2];
    const float* inscale = (const float*)d_in[3];
    float*       out     = (float*)d_out;
    (void)in_sizes; (void)n_in; (void)out_size;

    // 0) detect weight storage (int8 / int32 / float32) and normalize to int8
    detect_kernel<<<1, 256>>>((const int*)w);
    convert_w_kernel<<<((size_t)NN * KDIM / 4) / 256, 256>>>(w);

    // 1) quantize activations (32M floats, 4/thread)
    const int total4 = (MM * KDIM) / 4;
    quant_kernel<<<total4 / 256, 256>>>(x, inscale);

    // 2) int8 tensor-core GEMM + dequant
    cudaFuncSetAttribute(gemm_kernel, cudaFuncAttributeMaxDynamicSharedMemorySize,
                         SMEM_TOTAL);
    gemm_kernel<<<(MM / BM) * (NN / BN), THREADS, SMEM_TOTAL>>>(out, alpha);
}

// round 13
// speedup vs baseline: 1.0439x; 1.0439x over previous
#include <cuda_runtime.h>
#include <cstdint>

// ============================================================================
// out[M,N] = (clip(round(x/inscale)) int8) @ weight[N,K]^T * alpha
// M=8192, K=4096, N=4096.  Legacy-tensor-pipe bound (ncu: tensor=90.3%,
// occ=12.5%).  R10-R12: 3-stage pipeline (96KB) + 2 CTAs/SM to close the
// ~10% pipe-idle gap; single-buffered fragments (reg headroom at 128 cap).
// ============================================================================

#define MM 8192
#define NN 4096
#define KDIM 4096
#define BM 128
#define BN 128
#define BK 128                 // int8 elems (=bytes) per K-chunk
#define STAGES 3
#define THREADS 256
#define KITERS (KDIM / BK)     // 32

#define ASTAGE (BM * BK)                   // 16384 B
#define BSTAGE (BN * BK)                   // 16384 B
#define STAGE_BYTES (ASTAGE + BSTAGE)      // 32768 B
#define SMEM_TOTAL (STAGES * STAGE_BYTES)  // 98304 B -> 2 CTAs/SM

// device scratch (allocation-free)
__device__ int8_t g_q[(size_t)MM * (size_t)KDIM];   // quantized activations
__device__ int8_t g_w[(size_t)NN * (size_t)KDIM];   // normalized int8 weight
__device__ int    g_w_mode;                          // 0=int8, 1=int32, 2=f32

// ---------------------------------------------------------------------------
__device__ __forceinline__ uint32_t smem_u32(const void* p) {
    uint32_t a;
    asm("{ .reg .u64 t; cvta.to.shared.u64 t, %1; cvt.u32.u64 %0, t; }"
        : "=r"(a) : "l"(p));
    return a;
}

__device__ __forceinline__ void cp16(uint32_t dst, const void* src) {
    asm volatile("cp.async.cg.shared.global [%0], [%1], 16;"
                 :: "r"(dst), "l"(src));
}

#define CP_COMMIT() asm volatile("cp.async.commit_group;" ::: "memory")
#define CP_WAIT1()  asm volatile("cp.async.wait_group 1;" ::: "memory")

__device__ __forceinline__ uint32_t lds32(uint32_t addr) {
    uint32_t v;
    asm volatile("ld.shared.b32 %0, [%1];" : "=r"(v) : "r"(addr));
    return v;
}

__device__ __forceinline__ void mma_s8(int* c, const uint32_t* a, const uint32_t* b) {
    asm volatile(
        "mma.sync.aligned.m16n8k32.row.col.s32.s8.s8.s32 "
        "{%0,%1,%2,%3}, {%4,%5,%6,%7}, {%8,%9}, {%0,%1,%2,%3};"
        : "+r"(c[0]), "+r"(c[1]), "+r"(c[2]), "+r"(c[3])
        : "r"(a[0]), "r"(a[1]), "r"(a[2]), "r"(a[3]), "r"(b[0]), "r"(b[1]));
}

// XOR swizzle for 128-byte rows: chunk(16B) index ^= (row & 7).
// Same bijection for cp.async stores and fragment loads; conflict-free.
__device__ __forceinline__ uint32_t swz(int row, int chunk16) {
    return (uint32_t)(row * 128) + (uint32_t)((chunk16 ^ (row & 7)) * 16);
}

// ---------------------------------------------------------------------------
// Kernel 0a: detect weight storage format from the first 8192 32-bit words.
//   int32 storage: every word in [-128,127]        (raw int8: p ~ 2^-24/word)
//   float32 storage: every word is an integral-valued float, |v| <= 127
// Single block; writes the flag unconditionally every launch (deterministic).
// ---------------------------------------------------------------------------
__global__ void detect_kernel(const int* __restrict__ w) {
    __shared__ int cnt_i32, cnt_f32;
    if (threadIdx.x == 0) { cnt_i32 = 0; cnt_f32 = 0; }
    __syncthreads();
    int li = 0, lf = 0;
    for (int j = 0; j < 32; j++) {
        int v = w[threadIdx.x * 32 + j];
        if (v >= -128 && v <= 127) li++;
        float f = __int_as_float(v);
        if (f == rintf(f) && fabsf(f) <= 127.0f) lf++;
    }
    atomicAdd(&cnt_i32, li);
    atomicAdd(&cnt_f32, lf);
    __syncthreads();
    if (threadIdx.x == 0) {
        int mode = 0;
        if (cnt_i32 >= 4096) mode = 1;
        else if (cnt_f32 >= 4096) mode = 2;
        g_w_mode = mode;
    }
}

// Kernel 0b: normalize weight into int8 scratch.
__global__ void __launch_bounds__(256) convert_w_kernel(const void* __restrict__ w) {
    const size_t i = (size_t)blockIdx.x * blockDim.x + threadIdx.x;  // char4 idx
    const int mode = g_w_mode;
    char4 c;
    if (mode == 1) {
        int4 v = reinterpret_cast<const int4*>(w)[i];
        c.x = (char)v.x; c.y = (char)v.y; c.z = (char)v.z; c.w = (char)v.w;
    } else if (mode == 2) {
        float4 v = reinterpret_cast<const float4*>(w)[i];
        c.x = (char)(int)v.x; c.y = (char)(int)v.y;
        c.z = (char)(int)v.z; c.w = (char)(int)v.w;
    } else {
        c = reinterpret_cast<const char4*>(w)[i];
    }
    reinterpret_cast<char4*>(g_w)[i] = c;
}

// ---------------------------------------------------------------------------
// Kernel 1: fp32 -> int8 per-tensor quantization.
// __fdiv_rn: IEEE division even under --use_fast_math, so rintf() bit-matches
// jnp.round(xf / inscale) (round-half-even on the exact quotient).
// ---------------------------------------------------------------------------
__global__ void __launch_bounds__(256) quant_kernel(const float* __restrict__ x,
                                                    const float* __restrict__ inscale_p) {
    const float s = *inscale_p;
    size_t i = (size_t)blockIdx.x * blockDim.x + threadIdx.x;  // float4 index
    float4 v = reinterpret_cast<const float4*>(x)[i];
    char4 q;
    q.x = (char)(int)fminf(127.f, fmaxf(-128.f, rintf(__fdiv_rn(v.x, s))));
    q.y = (char)(int)fminf(127.f, fmaxf(-128.f, rintf(__fdiv_rn(v.y, s))));
    q.z = (char)(int)fminf(127.f, fmaxf(-128.f, rintf(__fdiv_rn(v.z, s))));
    q.w = (char)(int)fminf(127.f, fmaxf(-128.f, rintf(__fdiv_rn(v.w, s))));
    reinterpret_cast<char4*>(g_q)[i] = q;
}

// ---------------------------------------------------------------------------
// Kernel 2: int8 tensor-core GEMM (mma.sync) + fused alpha-dequant epilogue
// ---------------------------------------------------------------------------
__global__ void __launch_bounds__(THREADS, 2)
gemm_kernel(float* __restrict__ out, const float* __restrict__ alpha_p) {
    extern __shared__ char smem[];
    const uint32_t sbase = smem_u32(smem);
    const int tid = threadIdx.x;
    const int wid = tid >> 5;
    const int lid = tid & 31;

    // tile swizzle: groups of 16 M-tiles sweep all N-tiles (L2 reuse)
    const int grid_n = NN / BN;                 // 32
    const int pid = blockIdx.x;
    const int group = pid / (16 * grid_n);
    const int rem = pid % (16 * grid_n);
    const int tile_m = group * 16 + (rem & 15);
    const int tile_n = rem >> 4;
    const int m0 = tile_m * BM;
    const int n0 = tile_n * BN;

    const int warp_m = wid & 3;                 // 4 warps along M
    const int warp_n = wid >> 2;                // 2 warps along N

    const int8_t* aptr = g_q + (size_t)m0 * KDIM;
    const int8_t* bptr = g_w + (size_t)n0 * KDIM;

    int acc[2][8][4] = {};

    // PTX-ISA m16n8k32.s8 fragment addresses (explicit scalar loads):
    //  A a0: row = warp_m*32 + mi*16 + lid/4, k-bytes 4*(lid%4) of chunk 2ks
    //    a1: row+8 same chunk; a2/a3: chunk 2ks+1
    //  B b0: n = warp_n*64 + ni*8 + lid/4, chunk 2ks;  b1: chunk 2ks+1
    const int frow = lid >> 2;            // 0..7
    const int fbyte = (lid & 3) * 4;      // 0,4,8,12

    auto load_stage = [&](int kit, int stg) {
        const uint32_t abase = sbase + stg * STAGE_BYTES;
        const uint32_t bbase = abase + ASTAGE;
        const int kk0 = kit * BK;
#pragma unroll
        for (int i = 0; i < 4; i++) {           // A: 128 rows x 8 chunks
            int idx = tid + i * THREADS;
            int row = idx >> 3, c = idx & 7;
            cp16(abase + swz(row, c), aptr + (size_t)row * KDIM + kk0 + c * 16);
        }
#pragma unroll
        for (int i = 0; i < 4; i++) {           // B: 128 rows x 8 chunks
            int idx = tid + i * THREADS;
            int row = idx >> 3, c = idx & 7;
            cp16(bbase + swz(row, c), bptr + (size_t)row * KDIM + kk0 + c * 16);
        }
    };

    // single-buffered fragments: 4 warps/SMSP now hide the LDS latency
    auto compute_stage = [&](int stg) {
        const uint32_t abase = sbase + stg * STAGE_BYTES;
        const uint32_t bbase = abase + ASTAGE;
#pragma unroll
        for (int ks = 0; ks < 4; ks++) {
            const int c0 = ks * 2, c1 = ks * 2 + 1;
            uint32_t af[2][4];
#pragma unroll
            for (int mi = 0; mi < 2; mi++) {
                const int r = warp_m * 32 + mi * 16 + frow;
                af[mi][0] = lds32(abase + swz(r,     c0) + fbyte);
                af[mi][1] = lds32(abase + swz(r + 8, c0) + fbyte);
                af[mi][2] = lds32(abase + swz(r,     c1) + fbyte);
                af[mi][3] = lds32(abase + swz(r + 8, c1) + fbyte);
            }
            uint32_t bf[8][2];
#pragma unroll
            for (int ni = 0; ni < 8; ni++) {
                const int r = warp_n * 64 + ni * 8 + frow;
                bf[ni][0] = lds32(bbase + swz(r, c0) + fbyte);
                bf[ni][1] = lds32(bbase + swz(r, c1) + fbyte);
            }
#pragma unroll
            for (int mi = 0; mi < 2; mi++)
#pragma unroll
                for (int ni = 0; ni < 8; ni++)
                    mma_s8(acc[mi][ni], af[mi], bf[ni]);
        }
    };

    // prologue: fill STAGES-1 = 2 stages
#pragma unroll
    for (int s = 0; s < STAGES - 1; s++) {
        load_stage(s, s);
        CP_COMMIT();
    }

    for (int k = 0; k < KITERS; k++) {
        CP_WAIT1();          // stage k's group complete (<=1 group pending)
        __syncthreads();     // all warps done with the buffer we refill next
        const int kn = k + STAGES - 1;
        if (kn < KITERS) load_stage(kn, kn % STAGES);
        CP_COMMIT();         // (possibly empty group: keeps count aligned)
        compute_stage(k % STAGES);
    }

    // epilogue: alpha-dequant, float2 stores.
    // C fragment m16n8.s32: c0/c1 -> (row lid/4, col 2*(lid%4)+{0,1});
    //                       c2/c3 -> row+8, same cols.
    const float alpha = *alpha_p;
    const int r0 = m0 + warp_m * 32 + (lid >> 2);
    const int c0 = n0 + warp_n * 64 + (lid & 3) * 2;
#pragma unroll
    for (int mi = 0; mi < 2; mi++) {
#pragma unroll
        for (int ni = 0; ni < 8; ni++) {
            const int row = r0 + mi * 16;
            const int col = c0 + ni * 8;
            float2 v0, v1;
            v0.x = (float)acc[mi][ni][0] * alpha;
            v0.y = (float)acc[mi][ni][1] * alpha;
            v1.x = (float)acc[mi][ni][2] * alpha;
            v1.y = (float)acc[mi][ni][3] * alpha;
            *reinterpret_cast<float2*>(out + (size_t)row * NN + col) = v0;
            *reinterpret_cast<float2*>(out + (size_t)(row + 8) * NN + col) = v1;
        }
    }
}

// ---------------------------------------------------------------------------
extern "C" void kernel_launch(void* const* d_in, const int* in_sizes, int n_in,
                              void* d_out, int out_size) {
    const float* x       = (const float*)d_in[0];
    const void*  w       = d_in[1];
    const float* alpha   = (const float*)d_in[2];
    const float* inscale = (const float*)d_in[3];
    float*       out     = (float*)d_out;
    (void)in_sizes; (void)n_in; (void)out_size;

    // 0) detect weight storage (int8 / int32 / float32) and normalize to int8
    detect_kernel<<<1, 256>>>((const int*)w);
    convert_w_kernel<<<((size_t)NN * KDIM / 4) / 256, 256>>>(w);

    // 1) quantize activations (32M floats, 4/thread)
    const int total4 = (MM * KDIM) / 4;
    quant_kernel<<<total4 / 256, 256>>>(x, inscale);

    // 2) int8 tensor-core GEMM + dequant
    cudaFuncSetAttribute(gemm_kernel, cudaFuncAttributeMaxDynamicSharedMemorySize,
                         SMEM_TOTAL);
    gemm_kernel<<<(MM / BM) * (NN / BN), THREADS, SMEM_TOTAL>>>(out, alpha);
}